// round 16
// baseline (speedup 1.0000x reference)
#include <cuda_runtime.h>
#include <cuda_bf16.h>

#define Bz 4
#define Cc 256
#define Nn 4096
#define Rr 32
#define TK 64
#define SPLIT 2
#define KCHUNK (Nn / SPLIT)   // 2048 keys per split
#define NT (KCHUNK / TK)      // 32 key tiles per split
#define LOG2E 1.4426950408889634f

typedef unsigned long long ull;
typedef unsigned int uint32;
typedef unsigned short uint16;

// Scratch (static device arrays; no allocation anywhere)
__device__ __nv_bfloat16 g_Db[3][(size_t)Bz * Cc * Nn];            // depthwise outputs (bf16)
__device__ __align__(128) __nv_bfloat16 g_Fpb[3][(size_t)Bz * Nn * Rr];  // Q/K/V bf16 [b][n][r]
__device__ float g_Po[SPLIT][(size_t)Bz * Nn * Rr];                // attention partial numerators
__device__ float g_Pl[SPLIT][(size_t)Bz * Nn];                     // attention partial denominators

// ---- packed helpers -----------------------------------------------------------
__device__ __forceinline__ uint32 cvt2(float hi, float lo) {
    uint32 d; asm("cvt.rn.bf16x2.f32 %0, %1, %2;" : "=r"(d) : "f"(hi), "f"(lo)); return d;
}
__device__ __forceinline__ float ex2f(float x) {
    float d; asm("ex2.approx.ftz.f32 %0, %1;" : "=f"(d) : "f"(x)); return d;
}

// ---- cp.async helpers ---------------------------------------------------------
__device__ __forceinline__ void cpa16(uint32 dst, const void* src) {
    asm volatile("cp.async.cg.shared.global [%0], [%1], 16;" :: "r"(dst), "l"(src));
}
__device__ __forceinline__ void cpa_commit() {
    asm volatile("cp.async.commit_group;");
}
template <int N>
__device__ __forceinline__ void cpa_wait() {
    asm volatile("cp.async.wait_group %0;" :: "n"(N));
}

// ---- tensor-core helpers ----------------------------------------------------
__device__ __forceinline__ void ldsm4(uint32 r[4], uint32 addr) {
    asm volatile("ldmatrix.sync.aligned.m8n8.x4.shared.b16 {%0,%1,%2,%3}, [%4];"
        : "=r"(r[0]), "=r"(r[1]), "=r"(r[2]), "=r"(r[3]) : "r"(addr));
}
__device__ __forceinline__ void ldsm4t(uint32 r[4], uint32 addr) {
    asm volatile("ldmatrix.sync.aligned.m8n8.x4.trans.shared.b16 {%0,%1,%2,%3}, [%4];"
        : "=r"(r[0]), "=r"(r[1]), "=r"(r[2]), "=r"(r[3]) : "r"(addr));
}
__device__ __forceinline__ void mma16816(float c[4], const uint32 a[4], uint32 b0, uint32 b1) {
    asm volatile("mma.sync.aligned.m16n8k16.row.col.f32.bf16.bf16.f32 "
        "{%0,%1,%2,%3}, {%4,%5,%6,%7}, {%8,%9}, {%0,%1,%2,%3};"
        : "+f"(c[0]), "+f"(c[1]), "+f"(c[2]), "+f"(c[3])
        : "r"(a[0]), "r"(a[1]), "r"(a[2]), "r"(a[3]), "r"(b0), "r"(b1));
}
__device__ __forceinline__ int swz64(int x)  { return x ^ ((x >> 3) & 0x30); }  // 64B rows
__device__ __forceinline__ int swzB(int x)   { return x ^ ((x >> 4) & 0xF0); }  // 256B rows
__device__ __forceinline__ int swzW(int x)   { return x ^ ((x >> 5) & 0xF0); }  // 512B rows

// ---------------------------------------------------------------------------
// K1: fused depthwise 3x3 at dilations 1/3/5, register-blocked (R13).
// ---------------------------------------------------------------------------
template <int D>
__device__ __forceinline__ void dw_dil(const float* __restrict__ xs,
                                       const float* __restrict__ wk, float bias,
                                       int w, int B0, float* __restrict__ acc) {
#pragma unroll
    for (int r = 0; r < 16; r++) acc[r] = bias;
#pragma unroll
    for (int colk = 0; colk < 3; colk++) {
        int c = w + (colk - 1) * D;
        if ((unsigned)c < 64u) {
            float w0 = wk[colk], w1 = wk[3 + colk], w2 = wk[6 + colk];
#pragma unroll
            for (int jj = -D; jj < 16 + D; jj++) {
                int j = B0 + jj;
                if ((unsigned)j < 64u) {
                    float v = xs[(j << 6) + c];
                    if (jj - D >= 0 && jj - D < 16) acc[jj - D] = fmaf(w2, v, acc[jj - D]);
                    if (jj >= 0 && jj < 16)         acc[jj]     = fmaf(w1, v, acc[jj]);
                    if (jj + D >= 0 && jj + D < 16) acc[jj + D] = fmaf(w0, v, acc[jj + D]);
                }
            }
        }
    }
}

__global__ void __launch_bounds__(256) k_depthwise(const float* __restrict__ x,
                            const float* __restrict__ w1, const float* __restrict__ b1,
                            const float* __restrict__ w2, const float* __restrict__ b2,
                            const float* __restrict__ w3, const float* __restrict__ b3) {
    __shared__ float xs[Nn];
    int bc = blockIdx.x;
    int c = bc & (Cc - 1);
    const float* xp = x + (size_t)bc * Nn;
    for (int i = threadIdx.x; i < Nn; i += blockDim.x) xs[i] = xp[i];

    float wa[9], wb[9], wc[9];
#pragma unroll
    for (int i = 0; i < 9; i++) {
        wa[i] = __ldg(&w1[c * 9 + i]);
        wb[i] = __ldg(&w2[c * 9 + i]);
        wc[i] = __ldg(&w3[c * 9 + i]);
    }
    float biasa = __ldg(&b1[c]), biasb = __ldg(&b2[c]), biasc = __ldg(&b3[c]);

    const int w = threadIdx.x & 63;
    const int B0 = (threadIdx.x >> 6) * 16;
    __syncthreads();

    float acc[16];
    size_t base = (size_t)bc * Nn + (B0 << 6) + w;

    dw_dil<1>(xs, wa, biasa, w, B0, acc);
#pragma unroll
    for (int r = 0; r < 16; r++) g_Db[0][base + (r << 6)] = __float2bfloat16(acc[r]);

    dw_dil<3>(xs, wb, biasb, w, B0, acc);
#pragma unroll
    for (int r = 0; r < 16; r++) g_Db[1][base + (r << 6)] = __float2bfloat16(acc[r]);

    dw_dil<5>(xs, wc, biasc, w, B0, acc);
#pragma unroll
    for (int r = 0; r < 16; r++) g_Db[2][base + (r << 6)] = __float2bfloat16(acc[r]);
}

// ---------------------------------------------------------------------------
// K2: pointwise 1x1 C->R per branch on tensor cores (unchanged).
// ---------------------------------------------------------------------------
__global__ void __launch_bounds__(256) k_pointwise(
                            const float* __restrict__ pw1, const float* __restrict__ pb1,
                            const float* __restrict__ pw2, const float* __restrict__ pb2,
                            const float* __restrict__ pw3, const float* __restrict__ pb3) {
    __shared__ __align__(16) unsigned char sm[49152];
    const int t = threadIdx.x, lane = t & 31, w = t >> 5;
    const int k = blockIdx.z, b = blockIdx.y, n0 = blockIdx.x * 128;
    const float* pw = (k == 0) ? pw1 : ((k == 1) ? pw2 : pw3);
    const float* pb = (k == 0) ? pb1 : ((k == 1) ? pb2 : pb3);

    const uint32 smb = (uint32)__cvta_generic_to_shared(sm);
    const uint32 wsb = smb, tlb = smb + 16384;

    for (int id = t; id < 1024; id += 256) {
        int r = id >> 5;
        int ch = id & 31;
        const float4* src = (const float4*)(pw + r * 256 + ch * 8);
        float4 f0 = src[0], f1 = src[1];
        uint4 v = make_uint4(cvt2(f0.y, f0.x), cvt2(f0.w, f0.z),
                             cvt2(f1.y, f1.x), cvt2(f1.w, f1.z));
        *(uint4*)(sm + swzW(r * 512 + ch * 16)) = v;
    }

    float oac[2][2][4];
#pragma unroll
    for (int mb = 0; mb < 2; mb++)
#pragma unroll
        for (int nb = 0; nb < 2; nb++)
#pragma unroll
            for (int q = 0; q < 4; q++) oac[mb][nb][q] = 0.f;

    const __nv_bfloat16* Dbase = g_Db[k] + (size_t)b * Cc * Nn + n0;

#pragma unroll
    for (int cc = 0; cc < 2; cc++) {
        __syncthreads();
        for (int id = t; id < 2048; id += 256) {
            int cl = id >> 4, ch = id & 15;
            uint4 v = *(const uint4*)(Dbase + ((size_t)(cc * 128 + cl)) * Nn + ch * 8);
            *(uint4*)(sm + 16384 + swzB(cl * 256 + ch * 16)) = v;
        }
        __syncthreads();

#pragma unroll
        for (int ksl = 0; ksl < 8; ksl++) {
            int ks = cc * 8 + ksl;
            uint32 a0[4], a1[4], bb[4];
            ldsm4(a0, wsb + swzW((lane & 15) * 512 + ks * 32 + (lane >> 4) * 16));
            ldsm4(a1, wsb + swzW((16 + (lane & 15)) * 512 + ks * 32 + (lane >> 4) * 16));
            ldsm4t(bb, tlb + swzB((ksl * 16 + (lane & 15)) * 256 + w * 32 + (lane >> 4) * 16));
            mma16816(oac[0][0], a0, bb[0], bb[1]);
            mma16816(oac[0][1], a0, bb[2], bb[3]);
            mma16816(oac[1][0], a1, bb[0], bb[1]);
            mma16816(oac[1][1], a1, bb[2], bb[3]);
        }
    }

    const float scale = (k == 2) ? LOG2E : 1.0f;
    __syncthreads();
#pragma unroll
    for (int mb = 0; mb < 2; mb++) {
        int r0 = mb * 16 + (lane >> 2);
        float bias0 = __ldg(&pb[r0]);
        float bias1 = __ldg(&pb[r0 + 8]);
#pragma unroll
        for (int nb = 0; nb < 2; nb++) {
            int j0 = w * 16 + nb * 8 + (lane & 3) * 2;
            __nv_bfloat16* stg = (__nv_bfloat16*)(sm + 16384);
            stg[(j0 + 0) * 32 + r0]     = __float2bfloat16((oac[mb][nb][0] + bias0) * scale);
            stg[(j0 + 1) * 32 + r0]     = __float2bfloat16((oac[mb][nb][1] + bias0) * scale);
            stg[(j0 + 0) * 32 + r0 + 8] = __float2bfloat16((oac[mb][nb][2] + bias1) * scale);
            stg[(j0 + 1) * 32 + r0 + 8] = __float2bfloat16((oac[mb][nb][3] + bias1) * scale);
        }
    }
    __syncthreads();

    uint4* outg = (uint4*)g_Fpb[k];
    for (int id = t; id < 512; id += 256) {
        int n = id >> 2, part = id & 3;
        uint4 v = *(uint4*)(sm + 16384 + n * 64 + part * 16);
        outg[((size_t)b * Nn + n0 + n) * 4 + part] = v;
    }
}

// ---------------------------------------------------------------------------
// K3: flash attention on tensor cores. SPLIT=2 -> grid 256 blocks @2/SM
// fits the chip in a single wave (was 1.73 waves at SPLIT=4).
// ---------------------------------------------------------------------------
__global__ void __launch_bounds__(256, 2) k_attn() {
    __shared__ __align__(16) unsigned char sm[8192 + 2 * 8192];  // Q | (K,V)x2
    const int t = threadIdx.x, lane = t & 31, w = t >> 5;
    const int b = blockIdx.y, split = blockIdx.z;
    const int i0 = blockIdx.x * 128;

    const uint4* Qg = (const uint4*)(g_Fpb[1] + ((size_t)(b * Nn + i0)) * Rr);
#pragma unroll
    for (int id = t; id < 512; id += 256) {
        uint4 v = Qg[id];
        *(uint4*)(sm + swz64(id * 16)) = v;
    }
    __syncthreads();

    uint32 qbase = (uint32)__cvta_generic_to_shared(sm);

    uint32 qa[2][4];
#pragma unroll
    for (int kc = 0; kc < 2; kc++) {
        int row = w * 16 + (lane & 15);
        int chunk = 2 * kc + (lane >> 4);
        ldsm4(qa[kc], qbase + swz64(row * 64 + chunk * 16));
    }

    float oacc[4][4];
#pragma unroll
    for (int a = 0; a < 4; a++)
#pragma unroll
        for (int c = 0; c < 4; c++) oacc[a][c] = 0.f;
    float lsum0 = 0.f, lsum1 = 0.f;

    const uint4* Kg = (const uint4*)(g_Fpb[2] + (size_t)b * Nn * Rr);
    const uint4* Vg = (const uint4*)(g_Fpb[0] + (size_t)b * Nn * Rr);
    const int j0 = split * KCHUNK;
    const int kv_dst = swz64(t * 16);

    cpa16(qbase + 8192 + kv_dst,  Kg + (size_t)j0 * 4 + t);
    cpa16(qbase + 12288 + kv_dst, Vg + (size_t)j0 * 4 + t);
    cpa_commit();

    for (int tl = 0; tl < NT; tl++) {
        const int bufo = 8192 + (tl & 1) * 8192;
        const uint32 kbase = qbase + bufo, vbase = qbase + bufo + 4096;

        cpa_wait<0>();
        __syncthreads();

        if (tl + 1 < NT) {
            const int nbo = 8192 + ((tl + 1) & 1) * 8192;
            cpa16(qbase + nbo + kv_dst,        Kg + (size_t)(j0 + (tl + 1) * TK) * 4 + t);
            cpa16(qbase + nbo + 4096 + kv_dst, Vg + (size_t)(j0 + (tl + 1) * TK) * 4 + t);
            cpa_commit();
        }

        float sacc[8][4];
#pragma unroll
        for (int nb = 0; nb < 8; nb++)
#pragma unroll
            for (int c = 0; c < 4; c++) sacc[nb][c] = 0.f;

#pragma unroll
        for (int nb2 = 0; nb2 < 4; nb2++) {
#pragma unroll
            for (int ks = 0; ks < 2; ks++) {
                int row = nb2 * 16 + (lane & 7) + ((lane & 16) ? 8 : 0);
                int chunk = 2 * ks + ((lane >> 3) & 1);
                uint32 kb[4];
                ldsm4(kb, kbase + swz64(row * 64 + chunk * 16));
                mma16816(sacc[2 * nb2], qa[ks], kb[0], kb[1]);
                mma16816(sacc[2 * nb2 + 1], qa[ks], kb[2], kb[3]);
            }
        }

#pragma unroll
        for (int ks = 0; ks < 4; ks++) {
            uint32 pa[4];
            {
                int nb = 2 * ks;
                float e0 = ex2f(sacc[nb][0]), e1 = ex2f(sacc[nb][1]);
                float e2 = ex2f(sacc[nb][2]), e3 = ex2f(sacc[nb][3]);
                lsum0 += e0 + e1;
                lsum1 += e2 + e3;
                pa[0] = cvt2(e1, e0);
                pa[1] = cvt2(e3, e2);
            }
            {
                int nb = 2 * ks + 1;
                float e0 = ex2f(sacc[nb][0]), e1 = ex2f(sacc[nb][1]);
                float e2 = ex2f(sacc[nb][2]), e3 = ex2f(sacc[nb][3]);
                lsum0 += e0 + e1;
                lsum1 += e2 + e3;
                pa[2] = cvt2(e1, e0);
                pa[3] = cvt2(e3, e2);
            }
#pragma unroll
            for (int h = 0; h < 2; h++) {
                int row = ks * 16 + (lane & 15);
                int col = h * 16 + ((lane >> 4) * 8);
                uint32 vb[4];
                ldsm4t(vb, vbase + swz64(row * 64 + col * 2));
                mma16816(oacc[2 * h], pa, vb[0], vb[1]);
                mma16816(oacc[2 * h + 1], pa, vb[2], vb[3]);
            }
        }
    }

    lsum0 += __shfl_xor_sync(0xffffffffu, lsum0, 1);
    lsum0 += __shfl_xor_sync(0xffffffffu, lsum0, 2);
    lsum1 += __shfl_xor_sync(0xffffffffu, lsum1, 1);
    lsum1 += __shfl_xor_sync(0xffffffffu, lsum1, 2);

    int r = lane >> 2, c2 = 2 * (lane & 3);
    size_t rowbase = ((size_t)b * Nn + i0 + w * 16 + r) * Rr;
    float* Po = g_Po[split];
#pragma unroll
    for (int nb = 0; nb < 4; nb++) {
        *(float2*)(Po + rowbase + nb * 8 + c2) = make_float2(oacc[nb][0], oacc[nb][1]);
        *(float2*)(Po + rowbase + 8 * Rr + nb * 8 + c2) = make_float2(oacc[nb][2], oacc[nb][3]);
    }
    if ((lane & 3) == 0) {
        g_Pl[split][(size_t)b * Nn + i0 + w * 16 + r] = lsum0;
        g_Pl[split][(size_t)b * Nn + i0 + w * 16 + r + 8] = lsum1;
    }
}

// ---------------------------------------------------------------------------
// K4: split-combine + conv_out 1x1 (R->C) on tensor cores + bias + residual.
// co-split=2 (128 co per block) -> grid 1024 blocks (~55 warps/SM, was ~28).
// Grid (Nn/32, Bz, 2), 256 threads; warp owns 16 co rows.
// ---------------------------------------------------------------------------
__global__ void __launch_bounds__(256) k_out(const float* __restrict__ x,
                      const float* __restrict__ cow,
                      const float* __restrict__ cob, float* __restrict__ out) {
    __shared__ __align__(16) unsigned char sm[24576];
    // [0, 16384):   O tile bf16 (2KB, during mma) -> out-stage fp32 [128 co][32 n]
    // [16384, 24576): W bf16 [128 co][32 r], swz64 64B rows
    const int t = threadIdx.x, lane = t & 31, w = t >> 5;
    const int b = blockIdx.y, n0 = blockIdx.x * 32, co0 = blockIdx.z * 128;
    const uint32 smb = (uint32)__cvta_generic_to_shared(sm);
    const uint32 wsb = smb + 16384, osb = smb;

    // stage W: 128 co x 32 r fp32 -> bf16 swz64
    for (int id = t; id < 512; id += 256) {
        int r = id >> 2, ch = id & 3;
        const float4* src = (const float4*)(cow + (co0 + r) * 32 + ch * 8);
        float4 f0 = src[0], f1 = src[1];
        uint4 v = make_uint4(cvt2(f0.y, f0.x), cvt2(f0.w, f0.z),
                             cvt2(f1.y, f1.x), cvt2(f1.w, f1.z));
        *(uint4*)(sm + 16384 + swz64(r * 64 + ch * 16)) = v;
    }

    // combine split partials -> normalized bf16 O tile (one f4-chunk/thread)
    {
        int row = t >> 3, chunk = t & 7;
        size_t bn = (size_t)b * Nn + n0 + row;
        float l = 0.f;
#pragma unroll
        for (int s = 0; s < SPLIT; s++) l += g_Pl[s][bn];
        float inv = 1.0f / l;

        float4 acc = make_float4(0.f, 0.f, 0.f, 0.f);
#pragma unroll
        for (int s = 0; s < SPLIT; s++) {
            float4 v = ((const float4*)(g_Po[s] + bn * Rr))[chunk];
            acc.x += v.x; acc.y += v.y; acc.z += v.z; acc.w += v.w;
        }
        uint2 st;
        st.x = cvt2(acc.y * inv, acc.x * inv);
        st.y = cvt2(acc.w * inv, acc.z * inv);
        *(uint2*)(sm + swz64(row * 64 + chunk * 8)) = st;
    }
    __syncthreads();

    // A fragments: warp's 16 co rows, 2 k-steps
    uint32 a[2][4];
#pragma unroll
    for (int ks = 0; ks < 2; ks++)
        ldsm4(a[ks], wsb + swz64((w * 16 + (lane & 15)) * 64
                                 + (2 * ks + (lane >> 4)) * 16));

    float acc[4][4];
#pragma unroll
    for (int nb = 0; nb < 4; nb++)
#pragma unroll
        for (int q = 0; q < 4; q++) acc[nb][q] = 0.f;

#pragma unroll
    for (int ks = 0; ks < 2; ks++) {
#pragma unroll
        for (int nb2 = 0; nb2 < 2; nb2++) {
            int row = nb2 * 16 + (lane & 7) + ((lane & 16) ? 8 : 0);
            int chunk = 2 * ks + ((lane >> 3) & 1);
            uint32 kb[4];
            ldsm4(kb, osb + swz64(row * 64 + chunk * 16));
            mma16816(acc[2 * nb2],     a[ks], kb[0], kb[1]);
            mma16816(acc[2 * nb2 + 1], a[ks], kb[2], kb[3]);
        }
    }
    __syncthreads();    // all ldsm reads of the O region done before overwrite

    // fragments -> out-stage fp32 [co][n]
    float* stg = (float*)sm;
    {
        int row = w * 16 + (lane >> 2);
#pragma unroll
        for (int nb = 0; nb < 4; nb++) {
            int col = nb * 8 + 2 * (lane & 3);
            *(float2*)(stg + row * 32 + col)       = make_float2(acc[nb][0], acc[nb][1]);
            *(float2*)(stg + (row + 8) * 32 + col) = make_float2(acc[nb][2], acc[nb][3]);
        }
    }
    __syncthreads();

    // coalesced epilogue: out = x + stage + bias
    int j = t & 31, co_base = t >> 5;
#pragma unroll 4
    for (int i = 0; i < 16; i++) {
        int co = i * 8 + co_base;
        size_t off = ((size_t)(b * Cc + co0 + co)) * Nn + n0 + j;
        out[off] = x[off] + stg[co * 32 + j] + __ldg(&cob[co0 + co]);
    }
}

// ---------------------------------------------------------------------------
extern "C" void kernel_launch(void* const* d_in, const int* in_sizes, int n_in,
                              void* d_out, int out_size) {
    const float* x = (const float*)d_in[0];
    k_depthwise<<<Bz * Cc, 256>>>(x,
        (const float*)d_in[1], (const float*)d_in[2],
        (const float*)d_in[5], (const float*)d_in[6],
        (const float*)d_in[9], (const float*)d_in[10]);

    dim3 g2(Nn / 128, Bz, 3);
    k_pointwise<<<g2, 256>>>(
        (const float*)d_in[3],  (const float*)d_in[4],
        (const float*)d_in[7],  (const float*)d_in[8],
        (const float*)d_in[11], (const float*)d_in[12]);

    k_attn<<<dim3(Nn / 128, Bz, SPLIT), 256>>>();

    k_out<<<dim3(Nn / 32, Bz, 2), 256>>>(x, (const float*)d_in[13],
                                         (const float*)d_in[14], (float*)d_out);
}

// round 17
// speedup vs baseline: 1.0336x; 1.0336x over previous
#include <cuda_runtime.h>
#include <cuda_bf16.h>

#define Bz 4
#define Cc 256
#define Nn 4096
#define Rr 32
#define TK 64
#define SPLIT 2
#define KCHUNK (Nn / SPLIT)   // 2048 keys per split
#define NT (KCHUNK / TK)      // 32 key tiles per split
#define LOG2E 1.4426950408889634f

typedef unsigned long long ull;
typedef unsigned int uint32;
typedef unsigned short uint16;

// Scratch (static device arrays; no allocation anywhere)
__device__ __nv_bfloat16 g_Db[3][(size_t)Bz * Cc * Nn];            // depthwise outputs (bf16)
__device__ __align__(128) __nv_bfloat16 g_Fpb[3][(size_t)Bz * Nn * Rr];  // Q/K/V bf16 [b][n][r]
__device__ float g_Po[SPLIT][(size_t)Bz * Nn * Rr];                // attention partial numerators
__device__ float g_Pl[SPLIT][(size_t)Bz * Nn];                     // attention partial denominators

// ---- packed helpers -----------------------------------------------------------
__device__ __forceinline__ uint32 cvt2(float hi, float lo) {
    uint32 d; asm("cvt.rn.bf16x2.f32 %0, %1, %2;" : "=r"(d) : "f"(hi), "f"(lo)); return d;
}
__device__ __forceinline__ float ex2f(float x) {
    float d; asm("ex2.approx.ftz.f32 %0, %1;" : "=f"(d) : "f"(x)); return d;
}

// ---- cp.async helpers ---------------------------------------------------------
__device__ __forceinline__ void cpa16(uint32 dst, const void* src) {
    asm volatile("cp.async.cg.shared.global [%0], [%1], 16;" :: "r"(dst), "l"(src));
}
__device__ __forceinline__ void cpa_commit() {
    asm volatile("cp.async.commit_group;");
}
template <int N>
__device__ __forceinline__ void cpa_wait() {
    asm volatile("cp.async.wait_group %0;" :: "n"(N));
}

// ---- tensor-core helpers ----------------------------------------------------
__device__ __forceinline__ void ldsm4(uint32 r[4], uint32 addr) {
    asm volatile("ldmatrix.sync.aligned.m8n8.x4.shared.b16 {%0,%1,%2,%3}, [%4];"
        : "=r"(r[0]), "=r"(r[1]), "=r"(r[2]), "=r"(r[3]) : "r"(addr));
}
__device__ __forceinline__ void ldsm4t(uint32 r[4], uint32 addr) {
    asm volatile("ldmatrix.sync.aligned.m8n8.x4.trans.shared.b16 {%0,%1,%2,%3}, [%4];"
        : "=r"(r[0]), "=r"(r[1]), "=r"(r[2]), "=r"(r[3]) : "r"(addr));
}
__device__ __forceinline__ void mma16816(float c[4], const uint32 a[4], uint32 b0, uint32 b1) {
    asm volatile("mma.sync.aligned.m16n8k16.row.col.f32.bf16.bf16.f32 "
        "{%0,%1,%2,%3}, {%4,%5,%6,%7}, {%8,%9}, {%0,%1,%2,%3};"
        : "+f"(c[0]), "+f"(c[1]), "+f"(c[2]), "+f"(c[3])
        : "r"(a[0]), "r"(a[1]), "r"(a[2]), "r"(a[3]), "r"(b0), "r"(b1));
}
__device__ __forceinline__ int swz64(int x)  { return x ^ ((x >> 3) & 0x30); }  // 64B rows
__device__ __forceinline__ int swzB(int x)   { return x ^ ((x >> 4) & 0xF0); }  // 256B rows
__device__ __forceinline__ int swzW(int x)   { return x ^ ((x >> 5) & 0xF0); }  // 512B rows

// ---------------------------------------------------------------------------
// K1: fused depthwise 3x3 at dilations 1/3/5, register-blocked (R13).
// ---------------------------------------------------------------------------
template <int D>
__device__ __forceinline__ void dw_dil(const float* __restrict__ xs,
                                       const float* __restrict__ wk, float bias,
                                       int w, int B0, float* __restrict__ acc) {
#pragma unroll
    for (int r = 0; r < 16; r++) acc[r] = bias;
#pragma unroll
    for (int colk = 0; colk < 3; colk++) {
        int c = w + (colk - 1) * D;
        if ((unsigned)c < 64u) {
            float w0 = wk[colk], w1 = wk[3 + colk], w2 = wk[6 + colk];
#pragma unroll
            for (int jj = -D; jj < 16 + D; jj++) {
                int j = B0 + jj;
                if ((unsigned)j < 64u) {
                    float v = xs[(j << 6) + c];
                    if (jj - D >= 0 && jj - D < 16) acc[jj - D] = fmaf(w2, v, acc[jj - D]);
                    if (jj >= 0 && jj < 16)         acc[jj]     = fmaf(w1, v, acc[jj]);
                    if (jj + D >= 0 && jj + D < 16) acc[jj + D] = fmaf(w0, v, acc[jj + D]);
                }
            }
        }
    }
}

__global__ void __launch_bounds__(256) k_depthwise(const float* __restrict__ x,
                            const float* __restrict__ w1, const float* __restrict__ b1,
                            const float* __restrict__ w2, const float* __restrict__ b2,
                            const float* __restrict__ w3, const float* __restrict__ b3) {
    __shared__ float xs[Nn];
    int bc = blockIdx.x;
    int c = bc & (Cc - 1);
    const float* xp = x + (size_t)bc * Nn;
    for (int i = threadIdx.x; i < Nn; i += blockDim.x) xs[i] = xp[i];

    float wa[9], wb[9], wc[9];
#pragma unroll
    for (int i = 0; i < 9; i++) {
        wa[i] = __ldg(&w1[c * 9 + i]);
        wb[i] = __ldg(&w2[c * 9 + i]);
        wc[i] = __ldg(&w3[c * 9 + i]);
    }
    float biasa = __ldg(&b1[c]), biasb = __ldg(&b2[c]), biasc = __ldg(&b3[c]);

    const int w = threadIdx.x & 63;
    const int B0 = (threadIdx.x >> 6) * 16;
    __syncthreads();

    float acc[16];
    size_t base = (size_t)bc * Nn + (B0 << 6) + w;

    dw_dil<1>(xs, wa, biasa, w, B0, acc);
#pragma unroll
    for (int r = 0; r < 16; r++) g_Db[0][base + (r << 6)] = __float2bfloat16(acc[r]);

    dw_dil<3>(xs, wb, biasb, w, B0, acc);
#pragma unroll
    for (int r = 0; r < 16; r++) g_Db[1][base + (r << 6)] = __float2bfloat16(acc[r]);

    dw_dil<5>(xs, wc, biasc, w, B0, acc);
#pragma unroll
    for (int r = 0; r < 16; r++) g_Db[2][base + (r << 6)] = __float2bfloat16(acc[r]);
}

// ---------------------------------------------------------------------------
// K2: pointwise 1x1 C->R per branch on tensor cores (unchanged).
// ---------------------------------------------------------------------------
__global__ void __launch_bounds__(256) k_pointwise(
                            const float* __restrict__ pw1, const float* __restrict__ pb1,
                            const float* __restrict__ pw2, const float* __restrict__ pb2,
                            const float* __restrict__ pw3, const float* __restrict__ pb3) {
    __shared__ __align__(16) unsigned char sm[49152];
    const int t = threadIdx.x, lane = t & 31, w = t >> 5;
    const int k = blockIdx.z, b = blockIdx.y, n0 = blockIdx.x * 128;
    const float* pw = (k == 0) ? pw1 : ((k == 1) ? pw2 : pw3);
    const float* pb = (k == 0) ? pb1 : ((k == 1) ? pb2 : pb3);

    const uint32 smb = (uint32)__cvta_generic_to_shared(sm);
    const uint32 wsb = smb, tlb = smb + 16384;

    for (int id = t; id < 1024; id += 256) {
        int r = id >> 5;
        int ch = id & 31;
        const float4* src = (const float4*)(pw + r * 256 + ch * 8);
        float4 f0 = src[0], f1 = src[1];
        uint4 v = make_uint4(cvt2(f0.y, f0.x), cvt2(f0.w, f0.z),
                             cvt2(f1.y, f1.x), cvt2(f1.w, f1.z));
        *(uint4*)(sm + swzW(r * 512 + ch * 16)) = v;
    }

    float oac[2][2][4];
#pragma unroll
    for (int mb = 0; mb < 2; mb++)
#pragma unroll
        for (int nb = 0; nb < 2; nb++)
#pragma unroll
            for (int q = 0; q < 4; q++) oac[mb][nb][q] = 0.f;

    const __nv_bfloat16* Dbase = g_Db[k] + (size_t)b * Cc * Nn + n0;

#pragma unroll
    for (int cc = 0; cc < 2; cc++) {
        __syncthreads();
        for (int id = t; id < 2048; id += 256) {
            int cl = id >> 4, ch = id & 15;
            uint4 v = *(const uint4*)(Dbase + ((size_t)(cc * 128 + cl)) * Nn + ch * 8);
            *(uint4*)(sm + 16384 + swzB(cl * 256 + ch * 16)) = v;
        }
        __syncthreads();

#pragma unroll
        for (int ksl = 0; ksl < 8; ksl++) {
            int ks = cc * 8 + ksl;
            uint32 a0[4], a1[4], bb[4];
            ldsm4(a0, wsb + swzW((lane & 15) * 512 + ks * 32 + (lane >> 4) * 16));
            ldsm4(a1, wsb + swzW((16 + (lane & 15)) * 512 + ks * 32 + (lane >> 4) * 16));
            ldsm4t(bb, tlb + swzB((ksl * 16 + (lane & 15)) * 256 + w * 32 + (lane >> 4) * 16));
            mma16816(oac[0][0], a0, bb[0], bb[1]);
            mma16816(oac[0][1], a0, bb[2], bb[3]);
            mma16816(oac[1][0], a1, bb[0], bb[1]);
            mma16816(oac[1][1], a1, bb[2], bb[3]);
        }
    }

    const float scale = (k == 2) ? LOG2E : 1.0f;
    __syncthreads();
#pragma unroll
    for (int mb = 0; mb < 2; mb++) {
        int r0 = mb * 16 + (lane >> 2);
        float bias0 = __ldg(&pb[r0]);
        float bias1 = __ldg(&pb[r0 + 8]);
#pragma unroll
        for (int nb = 0; nb < 2; nb++) {
            int j0 = w * 16 + nb * 8 + (lane & 3) * 2;
            __nv_bfloat16* stg = (__nv_bfloat16*)(sm + 16384);
            stg[(j0 + 0) * 32 + r0]     = __float2bfloat16((oac[mb][nb][0] + bias0) * scale);
            stg[(j0 + 1) * 32 + r0]     = __float2bfloat16((oac[mb][nb][1] + bias0) * scale);
            stg[(j0 + 0) * 32 + r0 + 8] = __float2bfloat16((oac[mb][nb][2] + bias1) * scale);
            stg[(j0 + 1) * 32 + r0 + 8] = __float2bfloat16((oac[mb][nb][3] + bias1) * scale);
        }
    }
    __syncthreads();

    uint4* outg = (uint4*)g_Fpb[k];
    for (int id = t; id < 512; id += 256) {
        int n = id >> 2, part = id & 3;
        uint4 v = *(uint4*)(sm + 16384 + n * 64 + part * 16);
        outg[((size_t)b * Nn + n0 + n) * 4 + part] = v;
    }
}

// ---------------------------------------------------------------------------
// K3: flash attention on tensor cores, SPLIT=2 (single wave).
// ---------------------------------------------------------------------------
__global__ void __launch_bounds__(256, 2) k_attn() {
    __shared__ __align__(16) unsigned char sm[8192 + 2 * 8192];  // Q | (K,V)x2
    const int t = threadIdx.x, lane = t & 31, w = t >> 5;
    const int b = blockIdx.y, split = blockIdx.z;
    const int i0 = blockIdx.x * 128;

    const uint4* Qg = (const uint4*)(g_Fpb[1] + ((size_t)(b * Nn + i0)) * Rr);
#pragma unroll
    for (int id = t; id < 512; id += 256) {
        uint4 v = Qg[id];
        *(uint4*)(sm + swz64(id * 16)) = v;
    }
    __syncthreads();

    uint32 qbase = (uint32)__cvta_generic_to_shared(sm);

    uint32 qa[2][4];
#pragma unroll
    for (int kc = 0; kc < 2; kc++) {
        int row = w * 16 + (lane & 15);
        int chunk = 2 * kc + (lane >> 4);
        ldsm4(qa[kc], qbase + swz64(row * 64 + chunk * 16));
    }

    float oacc[4][4];
#pragma unroll
    for (int a = 0; a < 4; a++)
#pragma unroll
        for (int c = 0; c < 4; c++) oacc[a][c] = 0.f;
    float lsum0 = 0.f, lsum1 = 0.f;

    const uint4* Kg = (const uint4*)(g_Fpb[2] + (size_t)b * Nn * Rr);
    const uint4* Vg = (const uint4*)(g_Fpb[0] + (size_t)b * Nn * Rr);
    const int j0 = split * KCHUNK;
    const int kv_dst = swz64(t * 16);

    cpa16(qbase + 8192 + kv_dst,  Kg + (size_t)j0 * 4 + t);
    cpa16(qbase + 12288 + kv_dst, Vg + (size_t)j0 * 4 + t);
    cpa_commit();

    for (int tl = 0; tl < NT; tl++) {
        const int bufo = 8192 + (tl & 1) * 8192;
        const uint32 kbase = qbase + bufo, vbase = qbase + bufo + 4096;

        cpa_wait<0>();
        __syncthreads();

        if (tl + 1 < NT) {
            const int nbo = 8192 + ((tl + 1) & 1) * 8192;
            cpa16(qbase + nbo + kv_dst,        Kg + (size_t)(j0 + (tl + 1) * TK) * 4 + t);
            cpa16(qbase + nbo + 4096 + kv_dst, Vg + (size_t)(j0 + (tl + 1) * TK) * 4 + t);
            cpa_commit();
        }

        float sacc[8][4];
#pragma unroll
        for (int nb = 0; nb < 8; nb++)
#pragma unroll
            for (int c = 0; c < 4; c++) sacc[nb][c] = 0.f;

#pragma unroll
        for (int nb2 = 0; nb2 < 4; nb2++) {
#pragma unroll
            for (int ks = 0; ks < 2; ks++) {
                int row = nb2 * 16 + (lane & 7) + ((lane & 16) ? 8 : 0);
                int chunk = 2 * ks + ((lane >> 3) & 1);
                uint32 kb[4];
                ldsm4(kb, kbase + swz64(row * 64 + chunk * 16));
                mma16816(sacc[2 * nb2], qa[ks], kb[0], kb[1]);
                mma16816(sacc[2 * nb2 + 1], qa[ks], kb[2], kb[3]);
            }
        }

#pragma unroll
        for (int ks = 0; ks < 4; ks++) {
            uint32 pa[4];
            {
                int nb = 2 * ks;
                float e0 = ex2f(sacc[nb][0]), e1 = ex2f(sacc[nb][1]);
                float e2 = ex2f(sacc[nb][2]), e3 = ex2f(sacc[nb][3]);
                lsum0 += e0 + e1;
                lsum1 += e2 + e3;
                pa[0] = cvt2(e1, e0);
                pa[1] = cvt2(e3, e2);
            }
            {
                int nb = 2 * ks + 1;
                float e0 = ex2f(sacc[nb][0]), e1 = ex2f(sacc[nb][1]);
                float e2 = ex2f(sacc[nb][2]), e3 = ex2f(sacc[nb][3]);
                lsum0 += e0 + e1;
                lsum1 += e2 + e3;
                pa[2] = cvt2(e1, e0);
                pa[3] = cvt2(e3, e2);
            }
#pragma unroll
            for (int h = 0; h < 2; h++) {
                int row = ks * 16 + (lane & 15);
                int col = h * 16 + ((lane >> 4) * 8);
                uint32 vb[4];
                ldsm4t(vb, vbase + swz64(row * 64 + col * 2));
                mma16816(oacc[2 * h], pa, vb[0], vb[1]);
                mma16816(oacc[2 * h + 1], pa, vb[2], vb[3]);
            }
        }
    }

    lsum0 += __shfl_xor_sync(0xffffffffu, lsum0, 1);
    lsum0 += __shfl_xor_sync(0xffffffffu, lsum0, 2);
    lsum1 += __shfl_xor_sync(0xffffffffu, lsum1, 1);
    lsum1 += __shfl_xor_sync(0xffffffffu, lsum1, 2);

    int r = lane >> 2, c2 = 2 * (lane & 3);
    size_t rowbase = ((size_t)b * Nn + i0 + w * 16 + r) * Rr;
    float* Po = g_Po[split];
#pragma unroll
    for (int nb = 0; nb < 4; nb++) {
        *(float2*)(Po + rowbase + nb * 8 + c2) = make_float2(oacc[nb][0], oacc[nb][1]);
        *(float2*)(Po + rowbase + 8 * Rr + nb * 8 + c2) = make_float2(oacc[nb][2], oacc[nb][3]);
    }
    if ((lane & 3) == 0) {
        g_Pl[split][(size_t)b * Nn + i0 + w * 16 + r] = lsum0;
        g_Pl[split][(size_t)b * Nn + i0 + w * 16 + r + 8] = lsum1;
    }
}

// ---------------------------------------------------------------------------
// K4: split-combine + conv_out 1x1 (R->C) on tensor cores + bias + residual.
// Full 256 co per block (no work duplication); HMMA fragments written
// DIRECTLY to gmem fused with the residual (32B-sector-aligned per row),
// eliminating the fp32 smem stage and its scalar LDS epilogue.
// Grid (Nn/32, Bz), 256 threads.
// ---------------------------------------------------------------------------
__global__ void __launch_bounds__(256) k_out(const float* __restrict__ x,
                      const float* __restrict__ cow,
                      const float* __restrict__ cob, float* __restrict__ out) {
    __shared__ __align__(16) unsigned char sm[18432];
    // [0, 2048):      O tile bf16 [32 n][32 r] swz64
    // [2048, 18432):  W bf16 [256 co][32 r], swz64 64B rows
    const int t = threadIdx.x, lane = t & 31, w = t >> 5;
    const int b = blockIdx.y, n0 = blockIdx.x * 32;
    const uint32 smb = (uint32)__cvta_generic_to_shared(sm);
    const uint32 wsb = smb + 2048, osb = smb;

    // stage W: 256 co x 32 r fp32 -> bf16 swz64
    for (int id = t; id < 1024; id += 256) {
        int r = id >> 2, ch = id & 3;
        const float4* src = (const float4*)(cow + r * 32 + ch * 8);
        float4 f0 = src[0], f1 = src[1];
        uint4 v = make_uint4(cvt2(f0.y, f0.x), cvt2(f0.w, f0.z),
                             cvt2(f1.y, f1.x), cvt2(f1.w, f1.z));
        *(uint4*)(sm + 2048 + swz64(r * 64 + ch * 16)) = v;
    }

    // combine split partials -> normalized bf16 O tile (one f4-chunk/thread)
    {
        int row = t >> 3, chunk = t & 7;
        size_t bn = (size_t)b * Nn + n0 + row;
        float l = 0.f;
#pragma unroll
        for (int s = 0; s < SPLIT; s++) l += g_Pl[s][bn];
        float inv = 1.0f / l;

        float4 acc = make_float4(0.f, 0.f, 0.f, 0.f);
#pragma unroll
        for (int s = 0; s < SPLIT; s++) {
            float4 v = ((const float4*)(g_Po[s] + bn * Rr))[chunk];
            acc.x += v.x; acc.y += v.y; acc.z += v.z; acc.w += v.w;
        }
        uint2 st;
        st.x = cvt2(acc.y * inv, acc.x * inv);
        st.y = cvt2(acc.w * inv, acc.z * inv);
        *(uint2*)(sm + swz64(row * 64 + chunk * 8)) = st;
    }
    __syncthreads();

    // A fragments: warp's 32 co rows (2 m-blocks), 2 k-steps
    uint32 a[2][2][4];
#pragma unroll
    for (int mb = 0; mb < 2; mb++)
#pragma unroll
        for (int ks = 0; ks < 2; ks++)
            ldsm4(a[mb][ks], wsb + swz64((w * 32 + mb * 16 + (lane & 15)) * 64
                                         + (2 * ks + (lane >> 4)) * 16));

    float acc[2][4][4];
#pragma unroll
    for (int mb = 0; mb < 2; mb++)
#pragma unroll
        for (int nb = 0; nb < 4; nb++)
#pragma unroll
            for (int q = 0; q < 4; q++) acc[mb][nb][q] = 0.f;

#pragma unroll
    for (int ks = 0; ks < 2; ks++) {
#pragma unroll
        for (int nb2 = 0; nb2 < 2; nb2++) {
            int row = nb2 * 16 + (lane & 7) + ((lane & 16) ? 8 : 0);
            int chunk = 2 * ks + ((lane >> 3) & 1);
            uint32 kb[4];
            ldsm4(kb, osb + swz64(row * 64 + chunk * 16));
            mma16816(acc[0][2 * nb2],     a[0][ks], kb[0], kb[1]);
            mma16816(acc[0][2 * nb2 + 1], a[0][ks], kb[2], kb[3]);
            mma16816(acc[1][2 * nb2],     a[1][ks], kb[0], kb[1]);
            mma16816(acc[1][2 * nb2 + 1], a[1][ks], kb[2], kb[3]);
        }
    }

    // direct epilogue: fragments fused with residual, no smem stage.
    // fragment element (mb, nb, q): co = w*32 + mb*16 + (lane>>2) + (q>=2 ? 8:0)
    //                               n  = n0 + nb*8 + 2*(lane&3) + (q&1)
#pragma unroll
    for (int mb = 0; mb < 2; mb++) {
        int co = w * 32 + mb * 16 + (lane >> 2);
        float bias0 = __ldg(&cob[co]);
        float bias1 = __ldg(&cob[co + 8]);
        size_t base0 = ((size_t)(b * Cc + co)) * Nn + n0 + 2 * (lane & 3);
        size_t base1 = base0 + 8 * (size_t)Nn;
#pragma unroll
        for (int nb = 0; nb < 4; nb++) {
            size_t o0 = base0 + nb * 8;
            size_t o1 = base1 + nb * 8;
            float2 xv0 = *(const float2*)(x + o0);
            float2 xv1 = *(const float2*)(x + o1);
            *(float2*)(out + o0) = make_float2((xv0.x + acc[mb][nb][0]) + bias0,
                                               (xv0.y + acc[mb][nb][1]) + bias0);
            *(float2*)(out + o1) = make_float2((xv1.x + acc[mb][nb][2]) + bias1,
                                               (xv1.y + acc[mb][nb][3]) + bias1);
        }
    }
}

// ---------------------------------------------------------------------------
extern "C" void kernel_launch(void* const* d_in, const int* in_sizes, int n_in,
                              void* d_out, int out_size) {
    const float* x = (const float*)d_in[0];
    k_depthwise<<<Bz * Cc, 256>>>(x,
        (const float*)d_in[1], (const float*)d_in[2],
        (const float*)d_in[5], (const float*)d_in[6],
        (const float*)d_in[9], (const float*)d_in[10]);

    dim3 g2(Nn / 128, Bz, 3);
    k_pointwise<<<g2, 256>>>(
        (const float*)d_in[3],  (const float*)d_in[4],
        (const float*)d_in[7],  (const float*)d_in[8],
        (const float*)d_in[11], (const float*)d_in[12]);

    k_attn<<<dim3(Nn / 128, Bz, SPLIT), 256>>>();

    k_out<<<dim3(Nn / 32, Bz), 256>>>(x, (const float*)d_in[13],
                                      (const float*)d_in[14], (float*)d_out);
}